// round 2
// baseline (speedup 1.0000x reference)
#include <cuda_runtime.h>
#include <cuda_bf16.h>
#include <math.h>

// Problem constants
#define B_  4
#define N_  4096
#define C_  1024
#define H_  16
#define D_  64
#define M_TOT (B_ * N_)        // 16384 rows of the GEMM

// Scratch: o_mid in the SCRAMBLED layout (per-batch flat index h*N*d + n*d + dd),
// which row-major-viewed as [B*N, C] is exactly the GEMM A operand.
__device__ float g_omid[(size_t)B_ * N_ * C_];   // 64 MB

// ---------------------------------------------------------------------------
// Kernel 1: per-token head-to-head attention.
// One block (128 threads) per token. q from x, k=v from y.
// scores[h][g] = dot(q[h,:], k[g,:]) / 8 ; softmax over g ; o = p @ v.
// Writes o[b,n,h,dd] to g_omid at b*N*C + h*(N*D) + n*D + dd.
// ---------------------------------------------------------------------------
__global__ __launch_bounds__(128) void attn_kernel(
    const float* __restrict__ x,
    const float* __restrict__ y)
{
    const int t   = blockIdx.x;          // token id, 0..16383
    const int b   = t >> 12;             // /4096
    const int n   = t & 4095;
    const int tid = threadIdx.x;

    __shared__ float qs[H_ * 65];        // padded stride 65 (bank-conflict free)
    __shared__ float ks[H_ * 65];
    __shared__ float ps[H_ * H_];        // 16x16 probabilities

    const float* xrow = x + (size_t)t * C_;
    const float* yrow = y + (size_t)t * C_;

    // Load q and k/v rows into shared (coalesced), scatter into padded layout.
    #pragma unroll
    for (int i = 0; i < 8; i++) {
        int idx = tid + i * 128;         // 0..1023
        int h   = idx >> 6;
        int dd  = idx & 63;
        qs[h * 65 + dd] = xrow[idx];
        ks[h * 65 + dd] = yrow[idx];
    }
    __syncthreads();

    // Scores: 256 entries, 2 per thread.
    #pragma unroll
    for (int i = 0; i < 2; i++) {
        int e = tid + i * 128;           // 0..255
        int h = e >> 4;
        int g = e & 15;
        float s = 0.f;
        #pragma unroll
        for (int j = 0; j < D_; j++)
            s += qs[h * 65 + j] * ks[g * 65 + j];
        ps[h * 16 + g] = s * 0.125f;     // 1/sqrt(64)
    }
    __syncthreads();

    // Softmax over g: 16 threads, one row each.
    if (tid < H_) {
        float m = -1e30f;
        #pragma unroll
        for (int g = 0; g < H_; g++) m = fmaxf(m, ps[tid * 16 + g]);
        float sum = 0.f;
        float e[H_];
        #pragma unroll
        for (int g = 0; g < H_; g++) {
            e[g] = expf(ps[tid * 16 + g] - m);
            sum += e[g];
        }
        float inv = 1.f / sum;
        #pragma unroll
        for (int g = 0; g < H_; g++) ps[tid * 16 + g] = e[g] * inv;
    }
    __syncthreads();

    // o[h][dd] = sum_g p[h][g] * v[g][dd]; 8 outputs per thread; scattered store.
    const size_t base = (size_t)b * (N_ * C_) + (size_t)n * D_;
    #pragma unroll
    for (int i = 0; i < 8; i++) {
        int idx = tid + i * 128;         // 0..1023
        int h   = idx >> 6;
        int dd  = idx & 63;
        float acc = 0.f;
        #pragma unroll
        for (int g = 0; g < H_; g++)
            acc += ps[h * 16 + g] * ks[g * 65 + dd];
        g_omid[base + (size_t)h * (N_ * D_) + dd] = acc;
    }
}

// ---------------------------------------------------------------------------
// Kernel 2: SGEMM (NT): out[m][j] = sum_k A[m][k] * W[j][k] + bias[j]
// A = g_omid [16384, 1024] row-major, W [1024, 1024] row-major.
// 128x128 tile, BK=16, 256 threads, 8x8 per thread.
// ---------------------------------------------------------------------------
#define BM 128
#define BN 128
#define BK 16
#define TM 8
#define TN 8

__global__ __launch_bounds__(256) void proj_gemm_kernel(
    const float* __restrict__ A,
    const float* __restrict__ W,
    const float* __restrict__ bias,
    float* __restrict__ out,
    int M, int Nn, int K)
{
    __shared__ float As[BK][BM];
    __shared__ float Bs[BK][BN];

    const int tid = threadIdx.x;
    const int bm  = blockIdx.y * BM;
    const int bn  = blockIdx.x * BN;
    const int ty  = tid >> 4;            // 0..15
    const int tx  = tid & 15;            // 0..15
    const int row0 = ty * TM;
    const int col0 = tx * TN;

    float acc[TM][TN];
    #pragma unroll
    for (int i = 0; i < TM; i++)
        #pragma unroll
        for (int j = 0; j < TN; j++) acc[i][j] = 0.f;

    for (int k0 = 0; k0 < K; k0 += BK) {
        // Load tiles (each thread: 2x float4 from A, 2x float4 from W),
        // store transposed into smem.
        #pragma unroll
        for (int i = 0; i < 2; i++) {
            int idx = tid + i * 256;                 // 0..511
            int r   = idx >> 2;                      // row in tile 0..127
            int c4  = (idx & 3) * 4;                 // col 0,4,8,12
            float4 va = *(const float4*)(A + (size_t)(bm + r) * K + k0 + c4);
            As[c4 + 0][r] = va.x;
            As[c4 + 1][r] = va.y;
            As[c4 + 2][r] = va.z;
            As[c4 + 3][r] = va.w;
            float4 vb = *(const float4*)(W + (size_t)(bn + r) * K + k0 + c4);
            Bs[c4 + 0][r] = vb.x;
            Bs[c4 + 1][r] = vb.y;
            Bs[c4 + 2][r] = vb.z;
            Bs[c4 + 3][r] = vb.w;
        }
        __syncthreads();

        #pragma unroll
        for (int kk = 0; kk < BK; kk++) {
            float ar[TM], br[TN];
            #pragma unroll
            for (int i = 0; i < TM; i++) ar[i] = As[kk][row0 + i];
            #pragma unroll
            for (int j = 0; j < TN; j++) br[j] = Bs[kk][col0 + j];
            #pragma unroll
            for (int i = 0; i < TM; i++)
                #pragma unroll
                for (int j = 0; j < TN; j++)
                    acc[i][j] += ar[i] * br[j];
        }
        __syncthreads();
    }

    // Epilogue with bias, vectorized stores (float4).
    #pragma unroll
    for (int i = 0; i < TM; i++) {
        float* orow = out + (size_t)(bm + row0 + i) * Nn + bn + col0;
        #pragma unroll
        for (int j4 = 0; j4 < TN; j4 += 4) {
            float4 v;
            v.x = acc[i][j4 + 0] + bias[bn + col0 + j4 + 0];
            v.y = acc[i][j4 + 1] + bias[bn + col0 + j4 + 1];
            v.z = acc[i][j4 + 2] + bias[bn + col0 + j4 + 2];
            v.w = acc[i][j4 + 3] + bias[bn + col0 + j4 + 3];
            *(float4*)(orow + j4) = v;
        }
    }
}

// ---------------------------------------------------------------------------
extern "C" void kernel_launch(void* const* d_in, const int* in_sizes, int n_in,
                              void* d_out, int out_size)
{
    const float* x  = (const float*)d_in[0];   // [B, N, C]
    const float* y  = (const float*)d_in[1];   // [B, N, C]
    const float* Wp = (const float*)d_in[2];   // [C, C]
    const float* bp = (const float*)d_in[3];   // [C]
    float* out = (float*)d_out;                // [B, N, C]

    (void)in_sizes; (void)n_in; (void)out_size;

    float* omid;
    cudaGetSymbolAddress((void**)&omid, g_omid);

    // Kernel 1: attention + scrambled scatter
    attn_kernel<<<M_TOT, 128>>>(x, y);

    // Kernel 2: projection GEMM
    dim3 grid(C_ / BN, M_TOT / BM);   // (8, 128)
    proj_gemm_kernel<<<grid, 256>>>(omid, Wp, bp, out, M_TOT, C_, C_);
}

// round 12
// speedup vs baseline: 2.3023x; 2.3023x over previous
#include <cuda_runtime.h>
#include <cuda_bf16.h>
#include <math.h>
#include <stdint.h>

// Problem constants
#define B_  4
#define N_  4096
#define C_  1024
#define H_  16
#define D_  64
#define M_TOT (B_ * N_)        // 16384 rows of the GEMM

// ---------------------------------------------------------------------------
// Scratch (device globals; no allocation allowed)
// ---------------------------------------------------------------------------
__device__ __nv_bfloat16 g_Ah[(size_t)M_TOT * C_];   // 32 MB
__device__ __nv_bfloat16 g_Al[(size_t)M_TOT * C_];   // 32 MB
__device__ __nv_bfloat16 g_Wh[(size_t)C_ * C_];      // 2 MB
__device__ __nv_bfloat16 g_Wl[(size_t)C_ * C_];      // 2 MB

// ---------------------------------------------------------------------------
// Kernel 1: per-token head-to-head attention; emits bf16 hi/lo A operand
// in the SCRAMBLED layout (per-batch flat index h*N*d + n*d + dd).
// ---------------------------------------------------------------------------
__global__ __launch_bounds__(128) void attn_kernel(
    const float* __restrict__ x,
    const float* __restrict__ y)
{
    const int t   = blockIdx.x;
    const int b   = t >> 12;
    const int n   = t & 4095;
    const int tid = threadIdx.x;

    __shared__ float qs[H_ * 65];
    __shared__ float ks[H_ * 65];
    __shared__ float ps[H_ * H_];

    const float* xrow = x + (size_t)t * C_;
    const float* yrow = y + (size_t)t * C_;

    #pragma unroll
    for (int i = 0; i < 8; i++) {
        int idx = tid + i * 128;
        int h   = idx >> 6;
        int dd  = idx & 63;
        qs[h * 65 + dd] = xrow[idx];
        ks[h * 65 + dd] = yrow[idx];
    }
    __syncthreads();

    #pragma unroll
    for (int i = 0; i < 2; i++) {
        int e = tid + i * 128;
        int h = e >> 4;
        int g = e & 15;
        float s = 0.f;
        #pragma unroll
        for (int j = 0; j < D_; j++)
            s += qs[h * 65 + j] * ks[g * 65 + j];
        ps[h * 16 + g] = s * 0.125f;
    }
    __syncthreads();

    if (tid < H_) {
        float m = -1e30f;
        #pragma unroll
        for (int g = 0; g < H_; g++) m = fmaxf(m, ps[tid * 16 + g]);
        float sum = 0.f;
        float e[H_];
        #pragma unroll
        for (int g = 0; g < H_; g++) {
            e[g] = expf(ps[tid * 16 + g] - m);
            sum += e[g];
        }
        float inv = 1.f / sum;
        #pragma unroll
        for (int g = 0; g < H_; g++) ps[tid * 16 + g] = e[g] * inv;
    }
    __syncthreads();

    const size_t base = (size_t)b * (N_ * C_) + (size_t)n * D_;  // even
    #pragma unroll
    for (int i = 0; i < 4; i++) {
        int p   = tid + i * 128;       // 0..511
        int h   = p >> 5;              // 32 pairs per head
        int dd0 = (p & 31) * 2;
        float a0 = 0.f, a1 = 0.f;
        #pragma unroll
        for (int g = 0; g < H_; g++) {
            float pr = ps[h * 16 + g];
            a0 += pr * ks[g * 65 + dd0];
            a1 += pr * ks[g * 65 + dd0 + 1];
        }
        size_t oi = base + (size_t)h * (N_ * D_) + dd0;   // even
        __nv_bfloat16 h0 = __float2bfloat16(a0);
        __nv_bfloat16 h1 = __float2bfloat16(a1);
        ((__nv_bfloat162*)g_Ah)[oi >> 1] = __nv_bfloat162(h0, h1);
        ((__nv_bfloat162*)g_Al)[oi >> 1] = __nv_bfloat162(
            __float2bfloat16(a0 - __bfloat162float(h0)),
            __float2bfloat16(a1 - __bfloat162float(h1)));
    }
}

// ---------------------------------------------------------------------------
// Kernel 2: split W into bf16 hi/lo.
// ---------------------------------------------------------------------------
__global__ __launch_bounds__(256) void wsplit_kernel(const float* __restrict__ W)
{
    int i = blockIdx.x * 256 + threadIdx.x;     // over 1M/4 float4s
    float4 v = ((const float4*)W)[i];
    __nv_bfloat16 h0 = __float2bfloat16(v.x);
    __nv_bfloat16 h1 = __float2bfloat16(v.y);
    __nv_bfloat16 h2 = __float2bfloat16(v.z);
    __nv_bfloat16 h3 = __float2bfloat16(v.w);
    __nv_bfloat162* Wh2 = (__nv_bfloat162*)g_Wh;
    __nv_bfloat162* Wl2 = (__nv_bfloat162*)g_Wl;
    Wh2[i * 2 + 0] = __nv_bfloat162(h0, h1);
    Wh2[i * 2 + 1] = __nv_bfloat162(h2, h3);
    Wl2[i * 2 + 0] = __nv_bfloat162(
        __float2bfloat16(v.x - __bfloat162float(h0)),
        __float2bfloat16(v.y - __bfloat162float(h1)));
    Wl2[i * 2 + 1] = __nv_bfloat162(
        __float2bfloat16(v.z - __bfloat162float(h2)),
        __float2bfloat16(v.w - __bfloat162float(h3)));
}

// ---------------------------------------------------------------------------
// Kernel 3: split-bf16 GEMM via mma.sync.m16n8k16 (sm_80+ PTX, family-legal).
// out[m][j] = sum_k A[m][k]*W[j][k] + bias[j]
// CTA tile 128x128, BK=32, 8 warps (2 M x 4 N), warp tile 64x32.
// D += Ah*Wh + Al*Wh + Ah*Wl. cp.async double-buffered.
// ---------------------------------------------------------------------------
#define BK_T     32
#define NCHUNK   (C_ / BK_T)          // 32
#define PAD_ROW  40                   // bf16 elems per smem row (80 B, 16B-mult)
#define OP_ELEMS (128 * PAD_ROW)      // 5120 bf16 per operand tile
#define BUF_ELEMS (4 * OP_ELEMS)      // Ah, Al, Wh, Wl
#define SMEM_BYTES (2 * BUF_ELEMS * 2)   // 81920 B

__device__ __forceinline__ void cp16(uint32_t dst, const void* src) {
    asm volatile("cp.async.cg.shared.global [%0], [%1], 16;"
                 :: "r"(dst), "l"(src));
}
__device__ __forceinline__ void cp_commit() {
    asm volatile("cp.async.commit_group;");
}
template <int N>
__device__ __forceinline__ void cp_wait() {
    asm volatile("cp.async.wait_group %0;" :: "n"(N));
}

__device__ __forceinline__ void mma_bf16(float* c, const uint32_t* a,
                                         const uint32_t* b) {
    asm volatile(
        "mma.sync.aligned.m16n8k16.row.col.f32.bf16.bf16.f32 "
        "{%0,%1,%2,%3}, {%4,%5,%6,%7}, {%8,%9}, {%0,%1,%2,%3};"
        : "+f"(c[0]), "+f"(c[1]), "+f"(c[2]), "+f"(c[3])
        : "r"(a[0]), "r"(a[1]), "r"(a[2]), "r"(a[3]), "r"(b[0]), "r"(b[1]));
}

__device__ __forceinline__ uint32_t smem_u32(const void* p) {
    uint32_t a;
    asm("{ .reg .u64 t; cvta.to.shared.u64 t, %1; cvt.u32.u64 %0, t; }"
        : "=r"(a) : "l"(p));
    return a;
}

__global__ __launch_bounds__(256) void proj_gemm_mma(
    const __nv_bfloat16* __restrict__ Ah,
    const __nv_bfloat16* __restrict__ Al,
    const __nv_bfloat16* __restrict__ Wh,
    const __nv_bfloat16* __restrict__ Wl,
    const float* __restrict__ bias,
    float* __restrict__ out)
{
    extern __shared__ __nv_bfloat16 sm[];
    const uint32_t sbase = smem_u32(sm);

    const int tid = threadIdx.x;
    const int wid = tid >> 5;
    const int lid = tid & 31;
    const int g   = lid >> 2;          // groupID 0..7
    const int tig = lid & 3;           // thread-in-group 0..3
    const int wm  = wid & 1;           // warp M index (0..1)
    const int wn  = wid >> 1;          // warp N index (0..3)
    const int bm  = blockIdx.y * 128;
    const int bn  = blockIdx.x * 128;

    const __nv_bfloat16* Ah0 = Ah + (size_t)bm * C_;
    const __nv_bfloat16* Al0 = Al + (size_t)bm * C_;
    const __nv_bfloat16* Wh0 = Wh + (size_t)bn * C_;
    const __nv_bfloat16* Wl0 = Wl + (size_t)bn * C_;

    float acc[4][4][4];
    #pragma unroll
    for (int mi = 0; mi < 4; mi++)
        #pragma unroll
        for (int ni = 0; ni < 4; ni++)
            #pragma unroll
            for (int r = 0; r < 4; r++) acc[mi][ni][r] = 0.f;

    // ---- prefetch helper (8 x 16B cp.async per thread per chunk) ----
    const int prow = tid >> 2;         // 0..63 (base row, +64 on j=1)
    const int pc4  = tid & 3;          // 16B column 0..3
    auto prefetch = [&](int ch) {
        const int k0  = ch * BK_T;
        const uint32_t bufb = sbase + (uint32_t)(ch & 1) * (BUF_ELEMS * 2);
        #pragma unroll
        for (int j = 0; j < 2; j++) {
            int row = prow + j * 64;
            uint32_t doff = (uint32_t)row * (PAD_ROW * 2) + (uint32_t)pc4 * 16;
            size_t goff = (size_t)row * C_ + k0 + pc4 * 8;
            cp16(bufb + 0 * (OP_ELEMS * 2) + doff, Ah0 + goff);
            cp16(bufb + 1 * (OP_ELEMS * 2) + doff, Al0 + goff);
            cp16(bufb + 2 * (OP_ELEMS * 2) + doff, Wh0 + goff);
            cp16(bufb + 3 * (OP_ELEMS * 2) + doff, Wl0 + goff);
        }
    };

    prefetch(0);
    cp_commit();

    for (int ch = 0; ch < NCHUNK; ch++) {
        if (ch + 1 < NCHUNK) {
            prefetch(ch + 1);
            cp_commit();
            cp_wait<1>();
        } else {
            cp_wait<0>();
        }
        __syncthreads();

        const __nv_bfloat16* base = sm + (ch & 1) * BUF_ELEMS;
        const __nv_bfloat16* sAh = base;
        const __nv_bfloat16* sAl = base + OP_ELEMS;
        const __nv_bfloat16* sWh = base + 2 * OP_ELEMS;
        const __nv_bfloat16* sWl = base + 3 * OP_ELEMS;

        #pragma unroll
        for (int ks = 0; ks < 2; ks++) {
            const int kc = ks * 16 + tig * 2;

            uint32_t aH[4][4], aL[4][4];
            #pragma unroll
            for (int mi = 0; mi < 4; mi++) {
                const int r0 = wm * 64 + mi * 16 + g;
                const __nv_bfloat16* pH = sAh + r0 * PAD_ROW + kc;
                const __nv_bfloat16* pL = sAl + r0 * PAD_ROW + kc;
                aH[mi][0] = *(const uint32_t*)(pH);
                aH[mi][1] = *(const uint32_t*)(pH + 8 * PAD_ROW);
                aH[mi][2] = *(const uint32_t*)(pH + 8);
                aH[mi][3] = *(const uint32_t*)(pH + 8 * PAD_ROW + 8);
                aL[mi][0] = *(const uint32_t*)(pL);
                aL[mi][1] = *(const uint32_t*)(pL + 8 * PAD_ROW);
                aL[mi][2] = *(const uint32_t*)(pL + 8);
                aL[mi][3] = *(const uint32_t*)(pL + 8 * PAD_ROW + 8);
            }

            uint32_t bH[4][2], bL[4][2];
            #pragma unroll
            for (int ni = 0; ni < 4; ni++) {
                const int nr = wn * 32 + ni * 8 + g;
                const __nv_bfloat16* qH = sWh + nr * PAD_ROW + kc;
                const __nv_bfloat16* qL = sWl + nr * PAD_ROW + kc;
                bH[ni][0] = *(const uint32_t*)(qH);
                bH[ni][1] = *(const uint32_t*)(qH + 8);
                bL[ni][0] = *(const uint32_t*)(qL);
                bL[ni][1] = *(const uint32_t*)(qL + 8);
            }

            #pragma unroll
            for (int mi = 0; mi < 4; mi++)
                #pragma unroll
                for (int ni = 0; ni < 4; ni++) {
                    mma_bf16(acc[mi][ni], aH[mi], bH[ni]);
                    mma_bf16(acc[mi][ni], aL[mi], bH[ni]);
                    mma_bf16(acc[mi][ni], aH[mi], bL[ni]);
                }
        }
        __syncthreads();
    }

    // ---- epilogue: C frag mapping c0,c1=[g][2tig,2tig+1]; c2,c3=[g+8][..] ----
    #pragma unroll
    for (int mi = 0; mi < 4; mi++) {
        const int row0 = bm + wm * 64 + mi * 16 + g;
        #pragma unroll
        for (int ni = 0; ni < 4; ni++) {
            const int col = bn + wn * 32 + ni * 8 + tig * 2;
            const float2 bb = *(const float2*)(bias + col);
            float2 v0, v1;
            v0.x = acc[mi][ni][0] + bb.x;
            v0.y = acc[mi][ni][1] + bb.y;
            v1.x = acc[mi][ni][2] + bb.x;
            v1.y = acc[mi][ni][3] + bb.y;
            *(float2*)(out + (size_t)row0 * C_ + col) = v0;
            *(float2*)(out + (size_t)(row0 + 8) * C_ + col) = v1;
        }
    }
}

// ---------------------------------------------------------------------------
extern "C" void kernel_launch(void* const* d_in, const int* in_sizes, int n_in,
                              void* d_out, int out_size)
{
    const float* x  = (const float*)d_in[0];   // [B, N, C]
    const float* y  = (const float*)d_in[1];   // [B, N, C]
    const float* Wp = (const float*)d_in[2];   // [C, C]
    const float* bp = (const float*)d_in[3];   // [C]
    float* out = (float*)d_out;                // [B, N, C]
    (void)in_sizes; (void)n_in; (void)out_size;

    __nv_bfloat16 *Ah, *Al, *Wh, *Wl;
    cudaGetSymbolAddress((void**)&Ah, g_Ah);
    cudaGetSymbolAddress((void**)&Al, g_Al);
    cudaGetSymbolAddress((void**)&Wh, g_Wh);
    cudaGetSymbolAddress((void**)&Wl, g_Wl);

    cudaFuncSetAttribute(proj_gemm_mma,
                         cudaFuncAttributeMaxDynamicSharedMemorySize, SMEM_BYTES);

    attn_kernel<<<M_TOT, 128>>>(x, y);
    wsplit_kernel<<<(C_ * C_ / 4) / 256, 256>>>(Wp);

    dim3 grid(C_ / 128, M_TOT / 128);   // (8, 128) = 1024 CTAs
    proj_gemm_mma<<<grid, 256, SMEM_BYTES>>>(Ah, Al, Wh, Wl, bp, out);
}

// round 13
// speedup vs baseline: 4.0829x; 1.7733x over previous
#include <cuda_runtime.h>
#include <cuda_bf16.h>
#include <cuda_fp16.h>
#include <math.h>
#include <stdint.h>

// Problem constants
#define B_  4
#define N_  4096
#define C_  1024
#define H_  16
#define D_  64
#define M_TOT (B_ * N_)        // 16384 rows of the GEMM

// ---------------------------------------------------------------------------
// Scratch (device globals; no allocation allowed)
// A operand (fp16) in SCRAMBLED layout (per-batch flat h*N*d + n*d + dd),
// viewed row-major as [M_TOT, C_]. W operand (fp16) [C_, C_] row-major.
// fp16 single-term GEMM: factor RMS error ~2^-11.5 each -> output rel_err
// ~3-4e-4 (calibrated from measured 5.6e-6 of the bf16 3-term variant).
// ---------------------------------------------------------------------------
__device__ __half g_Af[(size_t)M_TOT * C_];   // 32 MB
__device__ __half g_Wf[(size_t)C_ * C_];      // 2 MB

// ---------------------------------------------------------------------------
// Kernel 1: per-token head-to-head attention; emits fp16 A operand.
// ---------------------------------------------------------------------------
__global__ __launch_bounds__(128) void attn_kernel(
    const float* __restrict__ x,
    const float* __restrict__ y)
{
    const int t   = blockIdx.x;
    const int b   = t >> 12;
    const int n   = t & 4095;
    const int tid = threadIdx.x;

    __shared__ float qs[H_ * 65];
    __shared__ float ks[H_ * 65];
    __shared__ float ps[H_ * H_];

    const float* xrow = x + (size_t)t * C_;
    const float* yrow = y + (size_t)t * C_;

    #pragma unroll
    for (int i = 0; i < 8; i++) {
        int idx = tid + i * 128;
        int h   = idx >> 6;
        int dd  = idx & 63;
        qs[h * 65 + dd] = xrow[idx];
        ks[h * 65 + dd] = yrow[idx];
    }
    __syncthreads();

    #pragma unroll
    for (int i = 0; i < 2; i++) {
        int e = tid + i * 128;
        int h = e >> 4;
        int g = e & 15;
        float s = 0.f;
        #pragma unroll
        for (int j = 0; j < D_; j++)
            s += qs[h * 65 + j] * ks[g * 65 + j];
        ps[h * 16 + g] = s * 0.125f;
    }
    __syncthreads();

    if (tid < H_) {
        float m = -1e30f;
        #pragma unroll
        for (int g = 0; g < H_; g++) m = fmaxf(m, ps[tid * 16 + g]);
        float sum = 0.f;
        float e[H_];
        #pragma unroll
        for (int g = 0; g < H_; g++) {
            e[g] = expf(ps[tid * 16 + g] - m);
            sum += e[g];
        }
        float inv = 1.f / sum;
        #pragma unroll
        for (int g = 0; g < H_; g++) ps[tid * 16 + g] = e[g] * inv;
    }
    __syncthreads();

    const size_t base = (size_t)b * (N_ * C_) + (size_t)n * D_;  // even
    #pragma unroll
    for (int i = 0; i < 4; i++) {
        int p   = tid + i * 128;       // 0..511
        int h   = p >> 5;              // 32 pairs per head
        int dd0 = (p & 31) * 2;
        float a0 = 0.f, a1 = 0.f;
        #pragma unroll
        for (int g = 0; g < H_; g++) {
            float pr = ps[h * 16 + g];
            a0 += pr * ks[g * 65 + dd0];
            a1 += pr * ks[g * 65 + dd0 + 1];
        }
        size_t oi = base + (size_t)h * (N_ * D_) + dd0;   // even
        ((__half2*)g_Af)[oi >> 1] = __floats2half2_rn(a0, a1);
    }
}

// ---------------------------------------------------------------------------
// Kernel 2: convert W to fp16.
// ---------------------------------------------------------------------------
__global__ __launch_bounds__(256) void wsplit_kernel(const float* __restrict__ W)
{
    int i = blockIdx.x * 256 + threadIdx.x;     // over 1M/4 float4s
    float4 v = ((const float4*)W)[i];
    __half2* Wf2 = (__half2*)g_Wf;
    Wf2[i * 2 + 0] = __floats2half2_rn(v.x, v.y);
    Wf2[i * 2 + 1] = __floats2half2_rn(v.z, v.w);
}

// ---------------------------------------------------------------------------
// Kernel 3: fp16 GEMM via mma.sync.m16n8k16 (fp32 accumulate).
// out[m][j] = sum_k A[m][k]*W[j][k] + bias[j]
// CTA tile 128x128, BK=32, 8 warps (2 M x 4 N), warp tile 64x32.
// cp.async double-buffered; 2 operand tiles (Af, Wf) per buffer.
// ---------------------------------------------------------------------------
#define BK_T     32
#define NCHUNK   (C_ / BK_T)          // 32
#define PAD_ROW  40                   // fp16 elems per smem row (80 B, 16B-mult)
#define OP_ELEMS (128 * PAD_ROW)      // 5120 fp16 per operand tile
#define BUF_ELEMS (2 * OP_ELEMS)      // Af, Wf
#define SMEM_BYTES (2 * BUF_ELEMS * 2)   // 40960 B

__device__ __forceinline__ void cp16(uint32_t dst, const void* src) {
    asm volatile("cp.async.cg.shared.global [%0], [%1], 16;"
                 :: "r"(dst), "l"(src));
}
__device__ __forceinline__ void cp_commit() {
    asm volatile("cp.async.commit_group;");
}
template <int N>
__device__ __forceinline__ void cp_wait() {
    asm volatile("cp.async.wait_group %0;" :: "n"(N));
}

__device__ __forceinline__ void mma_f16(float* c, const uint32_t* a,
                                        const uint32_t* b) {
    asm volatile(
        "mma.sync.aligned.m16n8k16.row.col.f32.f16.f16.f32 "
        "{%0,%1,%2,%3}, {%4,%5,%6,%7}, {%8,%9}, {%0,%1,%2,%3};"
        : "+f"(c[0]), "+f"(c[1]), "+f"(c[2]), "+f"(c[3])
        : "r"(a[0]), "r"(a[1]), "r"(a[2]), "r"(a[3]), "r"(b[0]), "r"(b[1]));
}

__device__ __forceinline__ uint32_t smem_u32(const void* p) {
    uint32_t a;
    asm("{ .reg .u64 t; cvta.to.shared.u64 t, %1; cvt.u32.u64 %0, t; }"
        : "=r"(a) : "l"(p));
    return a;
}

__global__ __launch_bounds__(256) void proj_gemm_mma(
    const __half* __restrict__ Af,
    const __half* __restrict__ Wf,
    const float* __restrict__ bias,
    float* __restrict__ out)
{
    extern __shared__ __half sm[];
    const uint32_t sbase = smem_u32(sm);

    const int tid = threadIdx.x;
    const int wid = tid >> 5;
    const int lid = tid & 31;
    const int g   = lid >> 2;          // groupID 0..7
    const int tig = lid & 3;           // thread-in-group 0..3
    const int wm  = wid & 1;           // warp M index (0..1)
    const int wn  = wid >> 1;          // warp N index (0..3)
    const int bm  = blockIdx.y * 128;
    const int bn  = blockIdx.x * 128;

    const __half* Af0 = Af + (size_t)bm * C_;
    const __half* Wf0 = Wf + (size_t)bn * C_;

    float acc[4][4][4];
    #pragma unroll
    for (int mi = 0; mi < 4; mi++)
        #pragma unroll
        for (int ni = 0; ni < 4; ni++)
            #pragma unroll
            for (int r = 0; r < 4; r++) acc[mi][ni][r] = 0.f;

    // ---- prefetch helper (4 x 16B cp.async per thread per chunk) ----
    const int prow = tid >> 2;         // 0..63 (base row, +64 on j=1)
    const int pc4  = tid & 3;          // 16B column 0..3
    auto prefetch = [&](int ch) {
        const int k0  = ch * BK_T;
        const uint32_t bufb = sbase + (uint32_t)(ch & 1) * (BUF_ELEMS * 2);
        #pragma unroll
        for (int j = 0; j < 2; j++) {
            int row = prow + j * 64;
            uint32_t doff = (uint32_t)row * (PAD_ROW * 2) + (uint32_t)pc4 * 16;
            size_t goff = (size_t)row * C_ + k0 + pc4 * 8;
            cp16(bufb + 0 * (OP_ELEMS * 2) + doff, Af0 + goff);
            cp16(bufb + 1 * (OP_ELEMS * 2) + doff, Wf0 + goff);
        }
    };

    prefetch(0);
    cp_commit();

    for (int ch = 0; ch < NCHUNK; ch++) {
        if (ch + 1 < NCHUNK) {
            prefetch(ch + 1);
            cp_commit();
            cp_wait<1>();
        } else {
            cp_wait<0>();
        }
        __syncthreads();

        const __half* base = sm + (ch & 1) * BUF_ELEMS;
        const __half* sAf = base;
        const __half* sWf = base + OP_ELEMS;

        #pragma unroll
        for (int ks = 0; ks < 2; ks++) {
            const int kc = ks * 16 + tig * 2;

            uint32_t aF[4][4];
            #pragma unroll
            for (int mi = 0; mi < 4; mi++) {
                const int r0 = wm * 64 + mi * 16 + g;
                const __half* pA = sAf + r0 * PAD_ROW + kc;
                aF[mi][0] = *(const uint32_t*)(pA);
                aF[mi][1] = *(const uint32_t*)(pA + 8 * PAD_ROW);
                aF[mi][2] = *(const uint32_t*)(pA + 8);
                aF[mi][3] = *(const uint32_t*)(pA + 8 * PAD_ROW + 8);
            }

            uint32_t bF[4][2];
            #pragma unroll
            for (int ni = 0; ni < 4; ni++) {
                const int nr = wn * 32 + ni * 8 + g;
                const __half* qW = sWf + nr * PAD_ROW + kc;
                bF[ni][0] = *(const uint32_t*)(qW);
                bF[ni][1] = *(const uint32_t*)(qW + 8);
            }

            #pragma unroll
            for (int mi = 0; mi < 4; mi++)
                #pragma unroll
                for (int ni = 0; ni < 4; ni++)
                    mma_f16(acc[mi][ni], aF[mi], bF[ni]);
        }
        __syncthreads();
    }

    // ---- epilogue: C frag mapping c0,c1=[g][2tig,2tig+1]; c2,c3=[g+8][..] ----
    #pragma unroll
    for (int mi = 0; mi < 4; mi++) {
        const int row0 = bm + wm * 64 + mi * 16 + g;
        #pragma unroll
        for (int ni = 0; ni < 4; ni++) {
            const int col = bn + wn * 32 + ni * 8 + tig * 2;
            const float2 bb = *(const float2*)(bias + col);
            float2 v0, v1;
            v0.x = acc[mi][ni][0] + bb.x;
            v0.y = acc[mi][ni][1] + bb.y;
            v1.x = acc[mi][ni][2] + bb.x;
            v1.y = acc[mi][ni][3] + bb.y;
            *(float2*)(out + (size_t)row0 * C_ + col) = v0;
            *(float2*)(out + (size_t)(row0 + 8) * C_ + col) = v1;
        }
    }
}

// ---------------------------------------------------------------------------
extern "C" void kernel_launch(void* const* d_in, const int* in_sizes, int n_in,
                              void* d_out, int out_size)
{
    const float* x  = (const float*)d_in[0];   // [B, N, C]
    const float* y  = (const float*)d_in[1];   // [B, N, C]
    const float* Wp = (const float*)d_in[2];   // [C, C]
    const float* bp = (const float*)d_in[3];   // [C]
    float* out = (float*)d_out;                // [B, N, C]
    (void)in_sizes; (void)n_in; (void)out_size;

    __half *Afp, *Wfp;
    cudaGetSymbolAddress((void**)&Afp, g_Af);
    cudaGetSymbolAddress((void**)&Wfp, g_Wf);

    cudaFuncSetAttribute(proj_gemm_mma,
                         cudaFuncAttributeMaxDynamicSharedMemorySize, SMEM_BYTES);

    attn_kernel<<<M_TOT, 128>>>(x, y);
    wsplit_kernel<<<(C_ * C_ / 4) / 256, 256>>>(Wp);

    dim3 grid(C_ / 128, M_TOT / 128);   // (8, 128) = 1024 CTAs
    proj_gemm_mma<<<grid, 256, SMEM_BYTES>>>(Afp, Wfp, bp, out);
}

// round 17
// speedup vs baseline: 4.2134x; 1.0320x over previous
#include <cuda_runtime.h>
#include <cuda_bf16.h>
#include <cuda_fp16.h>
#include <math.h>
#include <stdint.h>

// Problem constants
#define B_  4
#define N_  4096
#define C_  1024
#define H_  16
#define D_  64
#define M_TOT (B_ * N_)        // 16384 rows of the GEMM

// ---------------------------------------------------------------------------
// Scratch (device globals; no allocation allowed)
// ---------------------------------------------------------------------------
__device__ __half g_Af[(size_t)M_TOT * C_];   // 32 MB
__device__ __half g_Wf[(size_t)C_ * C_];      // 2 MB

// ---------------------------------------------------------------------------
// Kernel 1: per-token head-to-head attention; emits fp16 A operand.
// float4 global loads (4 x LDG.128 per thread instead of 16 x LDG.32).
// ---------------------------------------------------------------------------
__global__ __launch_bounds__(128) void attn_kernel(
    const float* __restrict__ x,
    const float* __restrict__ y)
{
    const int t   = blockIdx.x;
    const int b   = t >> 12;
    const int n   = t & 4095;
    const int tid = threadIdx.x;

    __shared__ float qs[H_ * 65];
    __shared__ float ks[H_ * 65];
    __shared__ float ps[H_ * H_];

    const float* xrow = x + (size_t)t * C_;
    const float* yrow = y + (size_t)t * C_;

    #pragma unroll
    for (int i = 0; i < 2; i++) {
        int i4 = tid + i * 128;        // float4 index 0..255
        int h  = i4 >> 4;
        int dd = (i4 & 15) * 4;
        float4 vx = ((const float4*)xrow)[i4];
        float4 vy = ((const float4*)yrow)[i4];
        float* q = &qs[h * 65 + dd];
        q[0] = vx.x; q[1] = vx.y; q[2] = vx.z; q[3] = vx.w;
        float* k = &ks[h * 65 + dd];
        k[0] = vy.x; k[1] = vy.y; k[2] = vy.z; k[3] = vy.w;
    }
    __syncthreads();

    #pragma unroll
    for (int i = 0; i < 2; i++) {
        int e = tid + i * 128;
        int h = e >> 4;
        int g = e & 15;
        float s = 0.f;
        #pragma unroll
        for (int j = 0; j < D_; j++)
            s += qs[h * 65 + j] * ks[g * 65 + j];
        ps[h * 16 + g] = s * 0.125f;
    }
    __syncthreads();

    if (tid < H_) {
        float m = -1e30f;
        #pragma unroll
        for (int g = 0; g < H_; g++) m = fmaxf(m, ps[tid * 16 + g]);
        float sum = 0.f;
        float e[H_];
        #pragma unroll
        for (int g = 0; g < H_; g++) {
            e[g] = expf(ps[tid * 16 + g] - m);
            sum += e[g];
        }
        float inv = 1.f / sum;
        #pragma unroll
        for (int g = 0; g < H_; g++) ps[tid * 16 + g] = e[g] * inv;
    }
    __syncthreads();

    const size_t base = (size_t)b * (N_ * C_) + (size_t)n * D_;  // even
    #pragma unroll
    for (int i = 0; i < 4; i++) {
        int p   = tid + i * 128;       // 0..511
        int h   = p >> 5;              // 32 pairs per head
        int dd0 = (p & 31) * 2;
        float a0 = 0.f, a1 = 0.f;
        #pragma unroll
        for (int g = 0; g < H_; g++) {
            float pr = ps[h * 16 + g];
            a0 += pr * ks[g * 65 + dd0];
            a1 += pr * ks[g * 65 + dd0 + 1];
        }
        size_t oi = base + (size_t)h * (N_ * D_) + dd0;   // even
        ((__half2*)g_Af)[oi >> 1] = __floats2half2_rn(a0, a1);
    }
}

// ---------------------------------------------------------------------------
// Kernel 2: convert W to fp16.
// ---------------------------------------------------------------------------
__global__ __launch_bounds__(256) void wsplit_kernel(const float* __restrict__ W)
{
    int i = blockIdx.x * 256 + threadIdx.x;     // over 1M/4 float4s
    float4 v = ((const float4*)W)[i];
    __half2* Wf2 = (__half2*)g_Wf;
    Wf2[i * 2 + 0] = __floats2half2_rn(v.x, v.y);
    Wf2[i * 2 + 1] = __floats2half2_rn(v.z, v.w);
}

// ---------------------------------------------------------------------------
// Kernel 3: fp16 GEMM via mma.sync.m16n8k16 (fp32 accumulate).
// out[m][j] = sum_k A[m][k]*W[j][k] + bias[j]
// CTA tile 128x128, BK=32, 8 warps (2 M x 4 N), warp tile 64x32.
// cp.async double-buffered; fragments loaded with ldmatrix.x4.
// ---------------------------------------------------------------------------
#define BK_T     32
#define NCHUNK   (C_ / BK_T)          // 32
#define PAD_ROW  40                   // fp16 elems per smem row (80 B, 16B-mult)
#define OP_ELEMS (128 * PAD_ROW)      // 5120 fp16 per operand tile
#define BUF_ELEMS (2 * OP_ELEMS)      // Af, Wf
#define SMEM_BYTES (2 * BUF_ELEMS * 2)   // 40960 B

__device__ __forceinline__ void cp16(uint32_t dst, const void* src) {
    asm volatile("cp.async.cg.shared.global [%0], [%1], 16;"
                 :: "r"(dst), "l"(src));
}
__device__ __forceinline__ void cp_commit() {
    asm volatile("cp.async.commit_group;");
}
template <int N>
__device__ __forceinline__ void cp_wait() {
    asm volatile("cp.async.wait_group %0;" :: "n"(N));
}

__device__ __forceinline__ void ldsm_x4(uint32_t& r0, uint32_t& r1,
                                        uint32_t& r2, uint32_t& r3,
                                        uint32_t addr) {
    asm volatile("ldmatrix.sync.aligned.m8n8.x4.shared.b16 {%0,%1,%2,%3}, [%4];"
                 : "=r"(r0), "=r"(r1), "=r"(r2), "=r"(r3) : "r"(addr));
}

__device__ __forceinline__ void mma_f16(float* c, const uint32_t* a,
                                        const uint32_t* b) {
    asm volatile(
        "mma.sync.aligned.m16n8k16.row.col.f32.f16.f16.f32 "
        "{%0,%1,%2,%3}, {%4,%5,%6,%7}, {%8,%9}, {%0,%1,%2,%3};"
        : "+f"(c[0]), "+f"(c[1]), "+f"(c[2]), "+f"(c[3])
        : "r"(a[0]), "r"(a[1]), "r"(a[2]), "r"(a[3]), "r"(b[0]), "r"(b[1]));
}

__device__ __forceinline__ uint32_t smem_u32(const void* p) {
    uint32_t a;
    asm("{ .reg .u64 t; cvta.to.shared.u64 t, %1; cvt.u32.u64 %0, t; }"
        : "=r"(a) : "l"(p));
    return a;
}

__global__ __launch_bounds__(256) void proj_gemm_mma(
    const __half* __restrict__ Af,
    const __half* __restrict__ Wf,
    const float* __restrict__ bias,
    float* __restrict__ out)
{
    extern __shared__ __half sm[];
    const uint32_t sbase = smem_u32(sm);

    const int tid = threadIdx.x;
    const int wid = tid >> 5;
    const int lid = tid & 31;
    const int g   = lid >> 2;          // groupID 0..7
    const int tig = lid & 3;           // thread-in-group 0..3
    const int wm  = wid & 1;           // warp M index (0..1)
    const int wn  = wid >> 1;          // warp N index (0..3)
    const int bm  = blockIdx.y * 128;
    const int bn  = blockIdx.x * 128;

    // ldmatrix per-lane addressing:
    // quad q = lid>>3 selects the 8x8 matrix; lane7 = row within matrix.
    const int lane7 = lid & 7;
    const int laneq = lid >> 3;        // 0..3
    // A: m0=rows+0/k+0, m1=rows+8/k+0, m2=rows+0/k+8, m3=rows+8/k+8
    const int aRow = wm * 64 + ((laneq & 1) << 3) + lane7;
    const int aCol = (laneq >> 1) << 3;
    // B (pair p covers ni=2p,2p+1): m0=b0(2p),m1=b1(2p),m2=b0(2p+1),m3=b1(2p+1)
    const int bRow = wn * 32 + ((laneq >> 1) << 3) + lane7;
    const int bCol = (laneq & 1) << 3;

    const __half* Af0 = Af + (size_t)bm * C_;
    const __half* Wf0 = Wf + (size_t)bn * C_;

    float acc[4][4][4];
    #pragma unroll
    for (int mi = 0; mi < 4; mi++)
        #pragma unroll
        for (int ni = 0; ni < 4; ni++)
            #pragma unroll
            for (int r = 0; r < 4; r++) acc[mi][ni][r] = 0.f;

    // ---- prefetch helper (4 x 16B cp.async per thread per chunk) ----
    const int prow = tid >> 2;         // 0..63 (base row, +64 on j=1)
    const int pc4  = tid & 3;          // 16B column 0..3
    auto prefetch = [&](int ch) {
        const int k0  = ch * BK_T;
        const uint32_t bufb = sbase + (uint32_t)(ch & 1) * (BUF_ELEMS * 2);
        #pragma unroll
        for (int j = 0; j < 2; j++) {
            int row = prow + j * 64;
            uint32_t doff = (uint32_t)row * (PAD_ROW * 2) + (uint32_t)pc4 * 16;
            size_t goff = (size_t)row * C_ + k0 + pc4 * 8;
            cp16(bufb + 0 * (OP_ELEMS * 2) + doff, Af0 + goff);
            cp16(bufb + 1 * (OP_ELEMS * 2) + doff, Wf0 + goff);
        }
    };

    prefetch(0);
    cp_commit();

    for (int ch = 0; ch < NCHUNK; ch++) {
        if (ch + 1 < NCHUNK) {
            prefetch(ch + 1);
            cp_commit();
            cp_wait<1>();
        } else {
            cp_wait<0>();
        }
        __syncthreads();

        const uint32_t bufb = sbase + (uint32_t)(ch & 1) * (BUF_ELEMS * 2);

        #pragma unroll
        for (int ks = 0; ks < 2; ks++) {
            const uint32_t kofs = (uint32_t)ks * 16;

            uint32_t aF[4][4];
            const uint32_t aAddr0 =
                bufb + ((uint32_t)aRow * PAD_ROW + kofs + aCol) * 2;
            #pragma unroll
            for (int mi = 0; mi < 4; mi++)
                ldsm_x4(aF[mi][0], aF[mi][1], aF[mi][2], aF[mi][3],
                        aAddr0 + (uint32_t)mi * (16 * PAD_ROW * 2));

            uint32_t bF[4][2];
            const uint32_t bAddr0 =
                bufb + OP_ELEMS * 2 + ((uint32_t)bRow * PAD_ROW + kofs + bCol) * 2;
            #pragma unroll
            for (int p = 0; p < 2; p++)
                ldsm_x4(bF[2 * p][0], bF[2 * p][1],
                        bF[2 * p + 1][0], bF[2 * p + 1][1],
                        bAddr0 + (uint32_t)p * (16 * PAD_ROW * 2));

            #pragma unroll
            for (int mi = 0; mi < 4; mi++)
                #pragma unroll
                for (int ni = 0; ni < 4; ni++)
                    mma_f16(acc[mi][ni], aF[mi], bF[ni]);
        }
        __syncthreads();
    }

    // ---- epilogue: C frag mapping c0,c1=[g][2tig,2tig+1]; c2,c3=[g+8][..] ----
    #pragma unroll
    for (int mi = 0; mi < 4; mi++) {
        const int row0 = bm + wm * 64 + mi * 16 + g;
        #pragma unroll
        for (int ni = 0; ni < 4; ni++) {
            const int col = bn + wn * 32 + ni * 8 + tig * 2;
            const float2 bb = *(const float2*)(bias + col);
            float2 v0, v1;
            v0.x = acc[mi][ni][0] + bb.x;
            v0.y = acc[mi][ni][1] + bb.y;
            v1.x = acc[mi][ni][2] + bb.x;
            v1.y = acc[mi][ni][3] + bb.y;
            *(float2*)(out + (size_t)row0 * C_ + col) = v0;
            *(float2*)(out + (size_t)(row0 + 8) * C_ + col) = v1;
        }
    }
}

// ---------------------------------------------------------------------------
extern "C" void kernel_launch(void* const* d_in, const int* in_sizes, int n_in,
                              void* d_out, int out_size)
{
    const float* x  = (const float*)d_in[0];   // [B, N, C]
    const float* y  = (const float*)d_in[1];   // [B, N, C]
    const float* Wp = (const float*)d_in[2];   // [C, C]
    const float* bp = (const float*)d_in[3];   // [C]
    float* out = (float*)d_out;                // [B, N, C]
    (void)in_sizes; (void)n_in; (void)out_size;

    __half *Afp, *Wfp;
    cudaGetSymbolAddress((void**)&Afp, g_Af);
    cudaGetSymbolAddress((void**)&Wfp, g_Wf);

    cudaFuncSetAttribute(proj_gemm_mma,
                         cudaFuncAttributeMaxDynamicSharedMemorySize, SMEM_BYTES);

    attn_kernel<<<M_TOT, 128>>>(x, y);
    wsplit_kernel<<<(C_ * C_ / 4) / 256, 256>>>(Wp);

    dim3 grid(C_ / 128, M_TOT / 128);   // (8, 128) = 1024 CTAs
    proj_gemm_mma<<<grid, 256, SMEM_BYTES>>>(Afp, Wfp, bp, out);
}